// round 3
// baseline (speedup 1.0000x reference)
#include <cuda_runtime.h>
#include <cuda_bf16.h>
#include <cstdint>

// Problem shape: N=40000 nodes, F_in=256, F_out=128, E=640000 edges.
static constexpr int MAXN = 40000;
static constexpr int MAXE = 640000;

// Scratch (allocation-free rule: __device__ globals)
__device__ int    g_is64;               // 1 if edge_index is int64, 0 if int32
__device__ int    g_cnt[MAXN];          // in-degree (edges only)
__device__ int    g_cur[MAXN];          // scatter cursors
__device__ int    g_rowptr[MAXN + 1];   // CSR row pointers (by dst)
__device__ float  g_dinv[MAXN];         // rsqrt(deg+1)
__device__ int    g_srcid[MAXE];        // CSR column (source node) ids
__device__ float4 g_xws[MAXN * 32];     // dinv[i] * (x @ W)[i], 32 float4 per row

// ---- packed f32x2 helpers ---------------------------------------------------
__device__ __forceinline__ unsigned long long pack2(float v) {
    unsigned long long r;
    asm("mov.b64 %0, {%1, %1};" : "=l"(r) : "f"(v));
    return r;
}
__device__ __forceinline__ unsigned long long fma2(unsigned long long a,
                                                   unsigned long long b,
                                                   unsigned long long c) {
    unsigned long long d;
    asm("fma.rn.f32x2 %0, %1, %2, %3;" : "=l"(d) : "l"(a), "l"(b), "l"(c));
    return d;
}
__device__ __forceinline__ void unpack2(unsigned long long p, float& lo, float& hi) {
    asm("mov.b64 {%0, %1}, %2;" : "=f"(lo), "=f"(hi) : "l"(p));
}

// ---------------------------------------------------------------------------
// 1) init: zero counters everywhere; block 0 additionally probes index dtype
//    (int64 indices in [0,40000) have all-zero high words).
__global__ void init_kernel(const int* __restrict__ ei32, int N) {
    int i = blockIdx.x * blockDim.x + threadIdx.x;
    if (i < N) { g_cnt[i] = 0; g_cur[i] = 0; }
    if (blockIdx.x == 0) {
        __shared__ int red[8];
        int tid = threadIdx.x;                   // 256 threads
        int acc = 0;
        for (int k = tid; k < 1024; k += 256)
            acc |= ei32[2 * k + 1];              // odd words = int64 high halves
        #pragma unroll
        for (int off = 16; off > 0; off >>= 1)
            acc |= __shfl_down_sync(0xFFFFFFFFu, acc, off);
        if ((tid & 31) == 0) red[tid >> 5] = acc;
        __syncthreads();
        if (tid == 0) {
            int r = 0;
            #pragma unroll
            for (int w = 0; w < 8; w++) r |= red[w];
            g_is64 = (r == 0) ? 1 : 0;
        }
    }
}

__device__ __forceinline__ int load_idx(const void* ei, long long i, int is64) {
    if (is64) return (int)((const long long*)ei)[i];
    return ((const int*)ei)[i];
}

// 2) histogram of dst (dst = elements [E, 2E) of edge_index)
__global__ void count_kernel(const void* __restrict__ ei, int E, int N) {
    int e = blockIdx.x * blockDim.x + threadIdx.x;
    if (e < E) {
        int is64 = g_is64;
        unsigned d = (unsigned)load_idx(ei, (long long)E + e, is64);
        if (d < (unsigned)N) atomicAdd(&g_cnt[d], 1);
    }
}

// 3) exclusive scan of g_cnt -> g_rowptr; fused dinv = rsqrt(deg+1)
__global__ void __launch_bounds__(1024) scan_kernel(int N) {
    __shared__ int shw[32];
    __shared__ int carry;
    int tid = threadIdx.x, lane = tid & 31, warp = tid >> 5;
    if (tid == 0) { carry = 0; g_rowptr[0] = 0; }
    __syncthreads();
    for (int base = 0; base < N; base += 1024) {
        int i = base + tid;
        int v = (i < N) ? g_cnt[i] : 0;
        if (i < N) g_dinv[i] = rsqrtf((float)v + 1.0f);
        int s = v;
        #pragma unroll
        for (int off = 1; off < 32; off <<= 1) {
            int t = __shfl_up_sync(0xFFFFFFFFu, s, off);
            if (lane >= off) s += t;
        }
        if (lane == 31) shw[warp] = s;
        __syncthreads();
        if (warp == 0) {
            int ws = shw[lane];
            #pragma unroll
            for (int off = 1; off < 32; off <<= 1) {
                int t = __shfl_up_sync(0xFFFFFFFFu, ws, off);
                if (lane >= off) ws += t;
            }
            shw[lane] = ws;
        }
        __syncthreads();
        int incl = s + (warp > 0 ? shw[warp - 1] : 0) + carry;
        if (i < N) g_rowptr[i + 1] = incl;
        __syncthreads();
        if (tid == 0) carry += shw[31];
        __syncthreads();
    }
}

// 4) scatter edge source ids into CSR slots
__global__ void scatter_kernel(const void* __restrict__ ei, int E, int N) {
    int e = blockIdx.x * blockDim.x + threadIdx.x;
    if (e < E) {
        int is64 = g_is64;
        unsigned d = (unsigned)load_idx(ei, (long long)E + e, is64);
        unsigned s = (unsigned)load_idx(ei, e, is64);
        if (d < (unsigned)N && s < (unsigned)N) {
            int pos = g_rowptr[d] + atomicAdd(&g_cur[d], 1);
            g_srcid[pos] = (int)s;
        }
    }
}

// ---------------------------------------------------------------------------
// 5) GEMM: xws[i,:] = dinv[i] * (x[i,:] @ W)    x:[N,256]  W:[256,128]
//    Tile 64x128, BK=32, 256 threads; thread tile 4 rows x 8 cols held as
//    packed f32x2 accumulators (FFMA2 via fma.rn.f32x2 doubles FMA throughput).
__global__ void __launch_bounds__(256) gemm_kernel(const float* __restrict__ x,
                                                   const float* __restrict__ W,
                                                   int N) {
    __shared__ float xs[64][36];       // [row][k], +4 pad (keeps 16B alignment)
    __shared__ float ws[32][128];      // [k][col]

    const int tid = threadIdx.x;
    const int jc  = tid & 15;          // col group: cols jc*8 .. jc*8+7
    const int rg  = tid >> 4;          // 0..15
    const int r0  = rg * 4;            // thread's first row in tile
    const int row0 = blockIdx.x * 64;

    const float4* X4 = (const float4*)x;   // row stride 64 float4
    const float4* W4 = (const float4*)W;   // row stride 32 float4

    unsigned long long acc[4][4];
    #pragma unroll
    for (int r = 0; r < 4; r++)
        #pragma unroll
        for (int j = 0; j < 4; j++) acc[r][j] = 0ULL;

    for (int k0 = 0; k0 < 256; k0 += 32) {
        // load x tile: 64 rows x 8 float4 = 512 float4, 2 per thread
        #pragma unroll
        for (int i = 0; i < 2; i++) {
            int idx = tid + i * 256;
            int r   = idx >> 3;
            int kq  = idx & 7;
            int rr  = min(row0 + r, N - 1);
            float4 v = X4[(size_t)rr * 64 + (k0 >> 2) + kq];
            *(float4*)&xs[r][kq * 4] = v;
        }
        // load W tile: 32 k x 32 float4 = 1024 float4, 4 per thread
        #pragma unroll
        for (int i = 0; i < 4; i++) {
            int idx = tid + i * 256;
            int k   = idx >> 5;
            int jq  = idx & 31;
            *(float4*)&ws[k][jq * 4] = W4[(size_t)(k0 + k) * 32 + jq];
        }
        __syncthreads();
        #pragma unroll
        for (int kk = 0; kk < 32; kk++) {
            ulonglong2 wA = *(const ulonglong2*)&ws[kk][jc * 8];
            ulonglong2 wB = *(const ulonglong2*)&ws[kk][jc * 8 + 4];
            #pragma unroll
            for (int r = 0; r < 4; r++) {
                unsigned long long xp = pack2(xs[r0 + r][kk]);
                acc[r][0] = fma2(xp, wA.x, acc[r][0]);
                acc[r][1] = fma2(xp, wA.y, acc[r][1]);
                acc[r][2] = fma2(xp, wB.x, acc[r][2]);
                acc[r][3] = fma2(xp, wB.y, acc[r][3]);
            }
        }
        __syncthreads();
    }

    #pragma unroll
    for (int r = 0; r < 4; r++) {
        int row = row0 + r0 + r;
        if (row < N) {
            float di = g_dinv[row];
            float o[8];
            #pragma unroll
            for (int j = 0; j < 4; j++) {
                float lo, hi;
                unpack2(acc[r][j], lo, hi);
                o[2 * j]     = lo * di;
                o[2 * j + 1] = hi * di;
            }
            g_xws[(size_t)row * 32 + jc * 2]     = make_float4(o[0], o[1], o[2], o[3]);
            g_xws[(size_t)row * 32 + jc * 2 + 1] = make_float4(o[4], o[5], o[6], o[7]);
        }
    }
}

// ---------------------------------------------------------------------------
// 6) aggregation: one warp per node.
//    out[i] = relu( dinv[i] * ( xws[i] + sum_{e: dst=i} xws[src[e]] ) + b )
__global__ void __launch_bounds__(256) agg_kernel(const float* __restrict__ b,
                                                  float* __restrict__ out, int N) {
    int warp = (blockIdx.x * blockDim.x + threadIdx.x) >> 5;
    int lane = threadIdx.x & 31;
    if (warp >= N) return;
    int node = warp;

    float4 acc = g_xws[(size_t)node * 32 + lane];   // self-loop contribution
    float4 bb  = ((const float4*)b)[lane];

    int e   = g_rowptr[node];
    int end = g_rowptr[node + 1];
    // 2-wide unroll: two independent L2 gathers in flight per iteration
    for (; e + 2 <= end; e += 2) {
        int s0 = g_srcid[e];
        int s1 = g_srcid[e + 1];
        float4 v0 = g_xws[(size_t)s0 * 32 + lane];
        float4 v1 = g_xws[(size_t)s1 * 32 + lane];
        acc.x += v0.x + v1.x;
        acc.y += v0.y + v1.y;
        acc.z += v0.z + v1.z;
        acc.w += v0.w + v1.w;
    }
    if (e < end) {
        int s = g_srcid[e];
        float4 v = g_xws[(size_t)s * 32 + lane];
        acc.x += v.x; acc.y += v.y; acc.z += v.z; acc.w += v.w;
    }

    float di = g_dinv[node];
    float4 o;
    o.x = fmaxf(fmaf(di, acc.x, bb.x), 0.f);
    o.y = fmaxf(fmaf(di, acc.y, bb.y), 0.f);
    o.z = fmaxf(fmaf(di, acc.z, bb.z), 0.f);
    o.w = fmaxf(fmaf(di, acc.w, bb.w), 0.f);
    ((float4*)out)[(size_t)node * 32 + lane] = o;
}

// ---------------------------------------------------------------------------
extern "C" void kernel_launch(void* const* d_in, const int* in_sizes, int n_in,
                              void* d_out, int out_size) {
    const float* x  = (const float*)d_in[0];
    const void*  ei = d_in[1];                 // [2, E] int32 or int64 (probed)
    const float* W  = (const float*)d_in[2];
    const float* b  = (const float*)d_in[3];
    float*       out = (float*)d_out;

    const int N = in_sizes[0] / 256;   // 40000
    const int E = in_sizes[1] / 2;     // 640000

    init_kernel<<<(N + 255) / 256, 256>>>((const int*)ei, N);
    count_kernel<<<(E + 255) / 256, 256>>>(ei, E, N);
    scan_kernel<<<1, 1024>>>(N);
    scatter_kernel<<<(E + 255) / 256, 256>>>(ei, E, N);
    gemm_kernel<<<(N + 63) / 64, 256>>>(x, W, N);
    agg_kernel<<<(N * 32 + 255) / 256, 256>>>(b, out, N);
}

// round 5
// speedup vs baseline: 1.1657x; 1.1657x over previous
#include <cuda_runtime.h>
#include <cuda_bf16.h>
#include <cstdint>

// Problem shape: N=40000 nodes, F_in=256, F_out=128, E=640000 edges.
static constexpr int MAXN = 40000;
static constexpr int MAXE = 640000;

// Scratch (allocation-free rule: __device__ globals)
__device__ int    g_is64;               // 1 if edge_index is int64, 0 if int32
__device__ int    g_cnt[MAXN];          // in-degree (edges only)
__device__ int    g_cur[MAXN];          // scatter cursors
__device__ int    g_rowptr[MAXN + 1];   // CSR row pointers (by dst)
__device__ float  g_dinv[MAXN];         // rsqrt(deg+1)
__device__ int    g_srcid[MAXE];        // CSR column (source node) ids
__device__ float4 g_xws[MAXN * 32];     // dinv[i] * (x @ W)[i], 32 float4 per row
// W^T split images: [n=128][k=256] bf16, hi and lo
__device__ __align__(16) __nv_bfloat16 g_wh[128 * 256];
__device__ __align__(16) __nv_bfloat16 g_wl[128 * 256];

// ---------------------------------------------------------------------------
__device__ __forceinline__ uint32_t smem_u32(const void* p) {
    uint32_t a;
    asm("{ .reg .u64 t; cvta.to.shared.u64 t, %1; cvt.u32.u64 %0, t; }" : "=r"(a) : "l"(p));
    return a;
}
#define LDSM_X4(r0, r1, r2, r3, adr)                                              \
    asm volatile("ldmatrix.sync.aligned.m8n8.x4.shared.b16 {%0,%1,%2,%3}, [%4];"  \
                 : "=r"(r0), "=r"(r1), "=r"(r2), "=r"(r3) : "r"(adr))
#define MMA_BF16(c, a, b)                                                         \
    asm volatile("mma.sync.aligned.m16n8k16.row.col.f32.bf16.bf16.f32 "           \
                 "{%0,%1,%2,%3}, {%4,%5,%6,%7}, {%8,%9}, {%0,%1,%2,%3};"          \
                 : "+f"((c)[0]), "+f"((c)[1]), "+f"((c)[2]), "+f"((c)[3])         \
                 : "r"((a)[0]), "r"((a)[1]), "r"((a)[2]), "r"((a)[3]),            \
                   "r"((b)[0]), "r"((b)[1]))

// ---------------------------------------------------------------------------
// 1) init: zero counters; block 0 probes index dtype; first 32768 threads
//    build W^T split-bf16 images.
__global__ void init_kernel(const int* __restrict__ ei32,
                            const float* __restrict__ W, int N) {
    int i = blockIdx.x * blockDim.x + threadIdx.x;
    if (i < N) { g_cnt[i] = 0; g_cur[i] = 0; }
    if (i < 128 * 256) {
        int k = i & 255;
        int n = i >> 8;
        float v = W[(size_t)k * 128 + n];
        __nv_bfloat16 hi = __float2bfloat16_rn(v);
        __nv_bfloat16 lo = __float2bfloat16_rn(v - __bfloat162float(hi));
        g_wh[n * 256 + k] = hi;
        g_wl[n * 256 + k] = lo;
    }
    if (blockIdx.x == 0) {
        __shared__ int red[8];
        int tid = threadIdx.x;
        int acc = 0;
        for (int k = tid; k < 1024; k += 256)
            acc |= ei32[2 * k + 1];              // int64 high halves
        #pragma unroll
        for (int off = 16; off > 0; off >>= 1)
            acc |= __shfl_down_sync(0xFFFFFFFFu, acc, off);
        if ((tid & 31) == 0) red[tid >> 5] = acc;
        __syncthreads();
        if (tid == 0) {
            int r = 0;
            #pragma unroll
            for (int w = 0; w < 8; w++) r |= red[w];
            g_is64 = (r == 0) ? 1 : 0;
        }
    }
}

__device__ __forceinline__ int load_idx(const void* ei, long long i, int is64) {
    if (is64) return (int)((const long long*)ei)[i];
    return ((const int*)ei)[i];
}

// 2) histogram of dst
__global__ void count_kernel(const void* __restrict__ ei, int E, int N) {
    int e = blockIdx.x * blockDim.x + threadIdx.x;
    if (e < E) {
        int is64 = g_is64;
        unsigned d = (unsigned)load_idx(ei, (long long)E + e, is64);
        if (d < (unsigned)N) atomicAdd(&g_cnt[d], 1);
    }
}

// 3) exclusive scan of g_cnt -> g_rowptr; fused dinv = rsqrt(deg+1)
__global__ void __launch_bounds__(1024) scan_kernel(int N) {
    __shared__ int shw[32];
    __shared__ int carry;
    int tid = threadIdx.x, lane = tid & 31, warp = tid >> 5;
    if (tid == 0) { carry = 0; g_rowptr[0] = 0; }
    __syncthreads();
    for (int base = 0; base < N; base += 1024) {
        int i = base + tid;
        int v = (i < N) ? g_cnt[i] : 0;
        if (i < N) g_dinv[i] = rsqrtf((float)v + 1.0f);
        int s = v;
        #pragma unroll
        for (int off = 1; off < 32; off <<= 1) {
            int t = __shfl_up_sync(0xFFFFFFFFu, s, off);
            if (lane >= off) s += t;
        }
        if (lane == 31) shw[warp] = s;
        __syncthreads();
        if (warp == 0) {
            int ws = shw[lane];
            #pragma unroll
            for (int off = 1; off < 32; off <<= 1) {
                int t = __shfl_up_sync(0xFFFFFFFFu, ws, off);
                if (lane >= off) ws += t;
            }
            shw[lane] = ws;
        }
        __syncthreads();
        int incl = s + (warp > 0 ? shw[warp - 1] : 0) + carry;
        if (i < N) g_rowptr[i + 1] = incl;
        __syncthreads();
        if (tid == 0) carry += shw[31];
        __syncthreads();
    }
}

// 4) scatter edge source ids into CSR slots
__global__ void scatter_kernel(const void* __restrict__ ei, int E, int N) {
    int e = blockIdx.x * blockDim.x + threadIdx.x;
    if (e < E) {
        int is64 = g_is64;
        unsigned d = (unsigned)load_idx(ei, (long long)E + e, is64);
        unsigned s = (unsigned)load_idx(ei, e, is64);
        if (d < (unsigned)N && s < (unsigned)N) {
            int pos = g_rowptr[d] + atomicAdd(&g_cur[d], 1);
            g_srcid[pos] = (int)s;
        }
    }
}

// ---------------------------------------------------------------------------
// 5) GEMM via mma.sync bf16 split: xws[i,:] = dinv[i] * (x[i,:] @ W)
//    CTA 128Mx128N, 8 warps (4Mx2N), warp 32Mx64N; K chunks of 64.
// SMEM: 4 images of [128][64 bf16 + 8 pad] -> 144B rows, 18432B each.
static constexpr int SM_AH  = 0;
static constexpr int SM_AL  = 18432;
static constexpr int SM_BH  = 36864;
static constexpr int SM_BL  = 55296;
static constexpr int SM_TOT = 73728;

__global__ void __launch_bounds__(256, 2)
gemm_kernel(const float* __restrict__ x, int N) {
    extern __shared__ unsigned char smc[];
    const uint32_t sm = smem_u32(smc);
    const int tid  = threadIdx.x;
    const int lane = tid & 31;
    const int wid  = tid >> 5;
    const int wm   = wid >> 1;          // 0..3 -> M offset wm*32
    const int wn   = wid & 1;           // 0..1 -> N offset wn*64
    const int row0 = blockIdx.x * 128;

    const float4* X4 = (const float4*)x;          // row stride 64 float4
    const uint4*  WH = (const uint4*)g_wh;        // row = 32 uint4
    const uint4*  WL = (const uint4*)g_wl;

    float acc[2][8][4];
    #pragma unroll
    for (int t = 0; t < 2; t++)
        #pragma unroll
        for (int nt = 0; nt < 8; nt++)
            #pragma unroll
            for (int j = 0; j < 4; j++) acc[t][nt][j] = 0.f;

    const int m = tid >> 1;             // producer row 0..127
    const int h = tid & 1;              // k-half (32 floats) within chunk
    const int rr = min(row0 + m, N - 1);

    // ldmatrix source addresses (fixed per thread, +32B per k-step)
    const uint32_t a_adr0 = sm + SM_AH + (wm * 32 + 0  + (lane & 15)) * 144 + ((lane >> 4) << 4);
    const uint32_t a_adr1 = sm + SM_AH + (wm * 32 + 16 + (lane & 15)) * 144 + ((lane >> 4) << 4);
    // B: per group j of 2 n-tiles
    const uint32_t b_row  = (uint32_t)(wn * 64 + ((lane >> 4) << 3) + (lane & 7));
    const uint32_t b_koff = (uint32_t)(((lane >> 3) & 1) << 4);
    const uint32_t b_adr  = sm + SM_BH + b_row * 144 + b_koff;

    for (int c = 0; c < 4; c++) {
        if (c > 0) __syncthreads();     // previous compute done before overwrite
        // ---- produce A (convert f32 -> split bf16) ----
        #pragma unroll
        for (int q = 0; q < 4; q++) {
            float4 f0 = X4[(size_t)rr * 64 + c * 16 + h * 8 + q * 2];
            float4 f1 = X4[(size_t)rr * 64 + c * 16 + h * 8 + q * 2 + 1];
            __nv_bfloat162 h0 = __floats2bfloat162_rn(f0.x, f0.y);
            __nv_bfloat162 h1 = __floats2bfloat162_rn(f0.z, f0.w);
            __nv_bfloat162 h2 = __floats2bfloat162_rn(f1.x, f1.y);
            __nv_bfloat162 h3 = __floats2bfloat162_rn(f1.z, f1.w);
            float2 a0 = __bfloat1622float2(h0);
            float2 a1 = __bfloat1622float2(h1);
            float2 a2 = __bfloat1622float2(h2);
            float2 a3 = __bfloat1622float2(h3);
            __nv_bfloat162 l0 = __floats2bfloat162_rn(f0.x - a0.x, f0.y - a0.y);
            __nv_bfloat162 l1 = __floats2bfloat162_rn(f0.z - a1.x, f0.w - a1.y);
            __nv_bfloat162 l2 = __floats2bfloat162_rn(f1.x - a2.x, f1.y - a2.y);
            __nv_bfloat162 l3 = __floats2bfloat162_rn(f1.z - a3.x, f1.w - a3.y);
            uint32_t off = (uint32_t)(m * 144 + h * 64 + q * 16);
            *(uint4*)(smc + SM_AH + off) = make_uint4(
                *(uint32_t*)&h0, *(uint32_t*)&h1, *(uint32_t*)&h2, *(uint32_t*)&h3);
            *(uint4*)(smc + SM_AL + off) = make_uint4(
                *(uint32_t*)&l0, *(uint32_t*)&l1, *(uint32_t*)&l2, *(uint32_t*)&l3);
        }
        // ---- copy B chunk (hi/lo), 4 uint4 each per thread ----
        #pragma unroll
        for (int it = 0; it < 4; it++) {
            int idx = tid + it * 256;          // 0..1023
            int n   = idx >> 3;
            int kq  = idx & 7;
            uint32_t dst = (uint32_t)(n * 144 + kq * 16);
            *(uint4*)(smc + SM_BH + dst) = WH[n * 32 + c * 8 + kq];
            *(uint4*)(smc + SM_BL + dst) = WL[n * 32 + c * 8 + kq];
        }
        __syncthreads();

        // ---- compute: 4 k16 steps ----
        #pragma unroll
        for (int ks = 0; ks < 4; ks++) {
            uint32_t ah0[4], ah1[4], al0[4], al1[4];
            LDSM_X4(ah0[0], ah0[1], ah0[2], ah0[3], a_adr0 + ks * 32);
            LDSM_X4(ah1[0], ah1[1], ah1[2], ah1[3], a_adr1 + ks * 32);
            LDSM_X4(al0[0], al0[1], al0[2], al0[3], a_adr0 + (SM_AL - SM_AH) + ks * 32);
            LDSM_X4(al1[0], al1[1], al1[2], al1[3], a_adr1 + (SM_AL - SM_AH) + ks * 32);
            #pragma unroll
            for (int j = 0; j < 4; j++) {      // 2 n-tiles per group
                uint32_t bh[4], bl[4];
                LDSM_X4(bh[0], bh[1], bh[2], bh[3], b_adr + j * 16 * 144 + ks * 32);
                LDSM_X4(bl[0], bl[1], bl[2], bl[3],
                        b_adr + (SM_BL - SM_BH) + j * 16 * 144 + ks * 32);
                MMA_BF16(acc[0][2 * j],     ah0, bh);
                MMA_BF16(acc[1][2 * j],     ah1, bh);
                MMA_BF16(acc[0][2 * j + 1], ah0, bh + 2);
                MMA_BF16(acc[1][2 * j + 1], ah1, bh + 2);
                MMA_BF16(acc[0][2 * j],     al0, bh);
                MMA_BF16(acc[1][2 * j],     al1, bh);
                MMA_BF16(acc[0][2 * j + 1], al0, bh + 2);
                MMA_BF16(acc[1][2 * j + 1], al1, bh + 2);
                MMA_BF16(acc[0][2 * j],     ah0, bl);
                MMA_BF16(acc[1][2 * j],     ah1, bl);
                MMA_BF16(acc[0][2 * j + 1], ah0, bl + 2);
                MMA_BF16(acc[1][2 * j + 1], ah1, bl + 2);
            }
        }
    }

    // ---- epilogue: scale by dinv[row], write g_xws ----
    float2* xw2 = (float2*)g_xws;
    const int nb2 = wn * 32;                    // n-base / 2
    #pragma unroll
    for (int t = 0; t < 2; t++) {
        int r_lo = row0 + wm * 32 + t * 16 + (lane >> 2);
        int r_hi = r_lo + 8;
        float d_lo = (r_lo < N) ? g_dinv[r_lo] : 0.f;
        float d_hi = (r_hi < N) ? g_dinv[r_hi] : 0.f;
        #pragma unroll
        for (int nt = 0; nt < 8; nt++) {
            int ci = nb2 + nt * 4 + (lane & 3);
            if (r_lo < N)
                xw2[(size_t)r_lo * 64 + ci] =
                    make_float2(acc[t][nt][0] * d_lo, acc[t][nt][1] * d_lo);
            if (r_hi < N)
                xw2[(size_t)r_hi * 64 + ci] =
                    make_float2(acc[t][nt][2] * d_hi, acc[t][nt][3] * d_hi);
        }
    }
}

// ---------------------------------------------------------------------------
// 6) aggregation: one warp per node.
__global__ void __launch_bounds__(256) agg_kernel(const float* __restrict__ b,
                                                  float* __restrict__ out, int N) {
    int warp = (blockIdx.x * blockDim.x + threadIdx.x) >> 5;
    int lane = threadIdx.x & 31;
    if (warp >= N) return;
    int node = warp;

    float4 acc = g_xws[(size_t)node * 32 + lane];   // self-loop contribution
    float4 bb  = ((const float4*)b)[lane];

    int e   = g_rowptr[node];
    int end = g_rowptr[node + 1];
    for (; e + 2 <= end; e += 2) {
        int s0 = g_srcid[e];
        int s1 = g_srcid[e + 1];
        float4 v0 = g_xws[(size_t)s0 * 32 + lane];
        float4 v1 = g_xws[(size_t)s1 * 32 + lane];
        acc.x += v0.x + v1.x;
        acc.y += v0.y + v1.y;
        acc.z += v0.z + v1.z;
        acc.w += v0.w + v1.w;
    }
    if (e < end) {
        int s = g_srcid[e];
        float4 v = g_xws[(size_t)s * 32 + lane];
        acc.x += v.x; acc.y += v.y; acc.z += v.z; acc.w += v.w;
    }

    float di = g_dinv[node];
    float4 o;
    o.x = fmaxf(fmaf(di, acc.x, bb.x), 0.f);
    o.y = fmaxf(fmaf(di, acc.y, bb.y), 0.f);
    o.z = fmaxf(fmaf(di, acc.z, bb.z), 0.f);
    o.w = fmaxf(fmaf(di, acc.w, bb.w), 0.f);
    ((float4*)out)[(size_t)node * 32 + lane] = o;
}

// ---------------------------------------------------------------------------
extern "C" void kernel_launch(void* const* d_in, const int* in_sizes, int n_in,
                              void* d_out, int out_size) {
    const float* x  = (const float*)d_in[0];
    const void*  ei = d_in[1];                 // [2, E] int32 or int64 (probed)
    const float* W  = (const float*)d_in[2];
    const float* b  = (const float*)d_in[3];
    float*       out = (float*)d_out;

    const int N = in_sizes[0] / 256;   // 40000
    const int E = in_sizes[1] / 2;     // 640000

    cudaFuncSetAttribute(gemm_kernel, cudaFuncAttributeMaxDynamicSharedMemorySize, SM_TOT);

    init_kernel<<<(N + 255) / 256, 256>>>((const int*)ei, W, N);
    count_kernel<<<(E + 255) / 256, 256>>>(ei, E, N);
    scan_kernel<<<1, 1024>>>(N);
    scatter_kernel<<<(E + 255) / 256, 256>>>(ei, E, N);
    gemm_kernel<<<(N + 127) / 128, 256, SM_TOT>>>(x, N);
    agg_kernel<<<(N * 32 + 255) / 256, 256>>>(b, out, N);
}

// round 6
// speedup vs baseline: 1.7853x; 1.5315x over previous
#include <cuda_runtime.h>
#include <cuda_bf16.h>
#include <cuda_fp16.h>
#include <cstdint>

// Problem shape: N=40000 nodes, F_in=256, F_out=128, E=640000 edges.
static constexpr int MAXN = 40000;
static constexpr int MAXE = 640000;

// Scratch (allocation-free rule: __device__ globals)
__device__ int    g_is64;               // 1 if edge_index is int64, 0 if int32
__device__ __align__(16) int g_cnt[MAXN];   // in-degree (edges only)
__device__ int    g_cur[MAXN];          // scatter cursors
__device__ int    g_rowptr[MAXN + 1];   // CSR row pointers (by dst)
__device__ float  g_dinv[MAXN];         // rsqrt(deg+1)
__device__ int    g_srcid[MAXE];        // CSR column (source node) ids
__device__ __align__(16) __half g_xwh[MAXN * 128];  // fp16 dinv[i]*(x@W)[i]
// W^T split images: [n=128][k=256] bf16, hi and lo
__device__ __align__(16) __nv_bfloat16 g_wh[128 * 256];
__device__ __align__(16) __nv_bfloat16 g_wl[128 * 256];

// ---------------------------------------------------------------------------
__device__ __forceinline__ uint32_t smem_u32(const void* p) {
    uint32_t a;
    asm("{ .reg .u64 t; cvta.to.shared.u64 t, %1; cvt.u32.u64 %0, t; }" : "=r"(a) : "l"(p));
    return a;
}
#define LDSM_X4(r0, r1, r2, r3, adr)                                              \
    asm volatile("ldmatrix.sync.aligned.m8n8.x4.shared.b16 {%0,%1,%2,%3}, [%4];"  \
                 : "=r"(r0), "=r"(r1), "=r"(r2), "=r"(r3) : "r"(adr))
#define MMA_BF16(c, a, b)                                                         \
    asm volatile("mma.sync.aligned.m16n8k16.row.col.f32.bf16.bf16.f32 "           \
                 "{%0,%1,%2,%3}, {%4,%5,%6,%7}, {%8,%9}, {%0,%1,%2,%3};"          \
                 : "+f"((c)[0]), "+f"((c)[1]), "+f"((c)[2]), "+f"((c)[3])         \
                 : "r"((a)[0]), "r"((a)[1]), "r"((a)[2]), "r"((a)[3]),            \
                   "r"((b)[0]), "r"((b)[1]))

// ---------------------------------------------------------------------------
// 1) init: zero counters; block 0 probes index dtype; first 32768 threads
//    build W^T split-bf16 images.
__global__ void init_kernel(const int* __restrict__ ei32,
                            const float* __restrict__ W, int N) {
    int i = blockIdx.x * blockDim.x + threadIdx.x;
    if (i < N) { g_cnt[i] = 0; g_cur[i] = 0; }
    if (i < 128 * 256) {
        int k = i & 255;
        int n = i >> 8;
        float v = W[(size_t)k * 128 + n];
        __nv_bfloat16 hi = __float2bfloat16_rn(v);
        __nv_bfloat16 lo = __float2bfloat16_rn(v - __bfloat162float(hi));
        g_wh[n * 256 + k] = hi;
        g_wl[n * 256 + k] = lo;
    }
    if (blockIdx.x == 0) {
        __shared__ int red[8];
        int tid = threadIdx.x;
        int acc = 0;
        for (int k = tid; k < 1024; k += 256)
            acc |= ei32[2 * k + 1];              // int64 high halves
        #pragma unroll
        for (int off = 16; off > 0; off >>= 1)
            acc |= __shfl_down_sync(0xFFFFFFFFu, acc, off);
        if ((tid & 31) == 0) red[tid >> 5] = acc;
        __syncthreads();
        if (tid == 0) {
            int r = 0;
            #pragma unroll
            for (int w = 0; w < 8; w++) r |= red[w];
            g_is64 = (r == 0) ? 1 : 0;
        }
    }
}

__device__ __forceinline__ int load_idx(const void* ei, long long i, int is64) {
    if (is64) return (int)((const long long*)ei)[i];
    return ((const int*)ei)[i];
}

// 2) histogram of dst
__global__ void count_kernel(const void* __restrict__ ei, int E, int N) {
    int e = blockIdx.x * blockDim.x + threadIdx.x;
    if (e < E) {
        int is64 = g_is64;
        unsigned d = (unsigned)load_idx(ei, (long long)E + e, is64);
        if (d < (unsigned)N) atomicAdd(&g_cnt[d], 1);
    }
}

// 3) exclusive scan of g_cnt -> g_rowptr; fused dinv. 4 elements/thread.
__global__ void __launch_bounds__(1024) scan_kernel(int N) {
    __shared__ int shw[32];
    __shared__ int carry;
    int tid = threadIdx.x, lane = tid & 31, warp = tid >> 5;
    if (tid == 0) { carry = 0; g_rowptr[0] = 0; }
    __syncthreads();
    for (int base = 0; base < N; base += 4096) {
        int i0 = base + tid * 4;
        int v[4];
        if (i0 + 3 < N) {
            int4 q = *(const int4*)&g_cnt[i0];
            v[0] = q.x; v[1] = q.y; v[2] = q.z; v[3] = q.w;
        } else {
            #pragma unroll
            for (int j = 0; j < 4; j++) v[j] = (i0 + j < N) ? g_cnt[i0 + j] : 0;
        }
        int tsum = v[0] + v[1] + v[2] + v[3];
        int s = tsum;
        #pragma unroll
        for (int off = 1; off < 32; off <<= 1) {
            int t = __shfl_up_sync(0xFFFFFFFFu, s, off);
            if (lane >= off) s += t;
        }
        if (lane == 31) shw[warp] = s;
        __syncthreads();
        if (warp == 0) {
            int ws = shw[lane];
            #pragma unroll
            for (int off = 1; off < 32; off <<= 1) {
                int t = __shfl_up_sync(0xFFFFFFFFu, ws, off);
                if (lane >= off) ws += t;
            }
            shw[lane] = ws;
        }
        __syncthreads();
        int run = (s - tsum) + (warp > 0 ? shw[warp - 1] : 0) + carry;
        #pragma unroll
        for (int j = 0; j < 4; j++) {
            run += v[j];
            if (i0 + j < N) {
                g_rowptr[i0 + j + 1] = run;
                g_dinv[i0 + j] = rsqrtf((float)v[j] + 1.0f);
            }
        }
        __syncthreads();
        if (tid == 0) carry += shw[31];
        __syncthreads();
    }
}

// 4) scatter edge source ids into CSR slots
__global__ void scatter_kernel(const void* __restrict__ ei, int E, int N) {
    int e = blockIdx.x * blockDim.x + threadIdx.x;
    if (e < E) {
        int is64 = g_is64;
        unsigned d = (unsigned)load_idx(ei, (long long)E + e, is64);
        unsigned s = (unsigned)load_idx(ei, e, is64);
        if (d < (unsigned)N && s < (unsigned)N) {
            int pos = g_rowptr[d] + atomicAdd(&g_cur[d], 1);
            g_srcid[pos] = (int)s;
        }
    }
}

// ---------------------------------------------------------------------------
// 5) GEMM via mma.sync bf16 split: xwh[i,:] = fp16( dinv[i] * (x[i,:] @ W) )
//    CTA 128Mx128N, 8 warps (4Mx2N), warp 32Mx64N; K chunks of 64.
//    Software pipeline: register-prefetch next A chunk during compute.
static constexpr int SM_AH  = 0;
static constexpr int SM_AL  = 18432;
static constexpr int SM_BH  = 36864;
static constexpr int SM_BL  = 55296;
static constexpr int SM_TOT = 73728;

__global__ void __launch_bounds__(256, 2)
gemm_kernel(const float* __restrict__ x, int N) {
    extern __shared__ unsigned char smc[];
    const uint32_t sm = smem_u32(smc);
    const int tid  = threadIdx.x;
    const int lane = tid & 31;
    const int wid  = tid >> 5;
    const int wm   = wid >> 1;          // 0..3 -> M offset wm*32
    const int wn   = wid & 1;           // 0..1 -> N offset wn*64
    const int row0 = blockIdx.x * 128;

    const float4* X4 = (const float4*)x;          // row stride 64 float4
    const uint4*  WH = (const uint4*)g_wh;        // row = 32 uint4
    const uint4*  WL = (const uint4*)g_wl;

    float acc[2][8][4];
    #pragma unroll
    for (int t = 0; t < 2; t++)
        #pragma unroll
        for (int nt = 0; nt < 8; nt++)
            #pragma unroll
            for (int j = 0; j < 4; j++) acc[t][nt][j] = 0.f;

    const int m = tid >> 1;             // producer row 0..127
    const int h = tid & 1;              // k-half (32 floats) within chunk
    const int rr = min(row0 + m, N - 1);

    const uint32_t a_adr0 = sm + SM_AH + (wm * 32 + 0  + (lane & 15)) * 144 + ((lane >> 4) << 4);
    const uint32_t a_adr1 = sm + SM_AH + (wm * 32 + 16 + (lane & 15)) * 144 + ((lane >> 4) << 4);
    const uint32_t b_row  = (uint32_t)(wn * 64 + ((lane >> 4) << 3) + (lane & 7));
    const uint32_t b_koff = (uint32_t)(((lane >> 3) & 1) << 4);
    const uint32_t b_adr  = sm + SM_BH + b_row * 144 + b_koff;

    float4 pre[8];
    #pragma unroll
    for (int q = 0; q < 8; q++)
        pre[q] = X4[(size_t)rr * 64 + h * 8 + q];

    for (int c = 0; c < 4; c++) {
        if (c > 0) __syncthreads();     // previous compute done before overwrite
        // ---- A: convert prefetched regs -> split bf16 -> STS ----
        #pragma unroll
        for (int q = 0; q < 4; q++) {
            float4 f0 = pre[q * 2];
            float4 f1 = pre[q * 2 + 1];
            __nv_bfloat162 h0 = __floats2bfloat162_rn(f0.x, f0.y);
            __nv_bfloat162 h1 = __floats2bfloat162_rn(f0.z, f0.w);
            __nv_bfloat162 h2 = __floats2bfloat162_rn(f1.x, f1.y);
            __nv_bfloat162 h3 = __floats2bfloat162_rn(f1.z, f1.w);
            float2 a0 = __bfloat1622float2(h0);
            float2 a1 = __bfloat1622float2(h1);
            float2 a2 = __bfloat1622float2(h2);
            float2 a3 = __bfloat1622float2(h3);
            __nv_bfloat162 l0 = __floats2bfloat162_rn(f0.x - a0.x, f0.y - a0.y);
            __nv_bfloat162 l1 = __floats2bfloat162_rn(f0.z - a1.x, f0.w - a1.y);
            __nv_bfloat162 l2 = __floats2bfloat162_rn(f1.x - a2.x, f1.y - a2.y);
            __nv_bfloat162 l3 = __floats2bfloat162_rn(f1.z - a3.x, f1.w - a3.y);
            uint32_t off = (uint32_t)(m * 144 + h * 64 + q * 16);
            *(uint4*)(smc + SM_AH + off) = make_uint4(
                *(uint32_t*)&h0, *(uint32_t*)&h1, *(uint32_t*)&h2, *(uint32_t*)&h3);
            *(uint4*)(smc + SM_AL + off) = make_uint4(
                *(uint32_t*)&l0, *(uint32_t*)&l1, *(uint32_t*)&l2, *(uint32_t*)&l3);
        }
        // ---- B chunk copy (hi/lo), 4 uint4 each per thread (L2-resident) ----
        #pragma unroll
        for (int it = 0; it < 4; it++) {
            int idx = tid + it * 256;          // 0..1023
            int n   = idx >> 3;
            int kq  = idx & 7;
            uint32_t dst = (uint32_t)(n * 144 + kq * 16);
            *(uint4*)(smc + SM_BH + dst) = WH[n * 32 + c * 8 + kq];
            *(uint4*)(smc + SM_BL + dst) = WL[n * 32 + c * 8 + kq];
        }
        __syncthreads();

        // ---- prefetch next A chunk (latency hidden by mma loop) ----
        if (c < 3) {
            #pragma unroll
            for (int q = 0; q < 8; q++)
                pre[q] = X4[(size_t)rr * 64 + (c + 1) * 16 + h * 8 + q];
        }

        // ---- compute: 4 k16 steps ----
        #pragma unroll
        for (int ks = 0; ks < 4; ks++) {
            uint32_t ah0[4], ah1[4], al0[4], al1[4];
            LDSM_X4(ah0[0], ah0[1], ah0[2], ah0[3], a_adr0 + ks * 32);
            LDSM_X4(ah1[0], ah1[1], ah1[2], ah1[3], a_adr1 + ks * 32);
            LDSM_X4(al0[0], al0[1], al0[2], al0[3], a_adr0 + (SM_AL - SM_AH) + ks * 32);
            LDSM_X4(al1[0], al1[1], al1[2], al1[3], a_adr1 + (SM_AL - SM_AH) + ks * 32);
            #pragma unroll
            for (int j = 0; j < 4; j++) {      // 2 n-tiles per group
                uint32_t bh[4], bl[4];
                LDSM_X4(bh[0], bh[1], bh[2], bh[3], b_adr + j * 16 * 144 + ks * 32);
                LDSM_X4(bl[0], bl[1], bl[2], bl[3],
                        b_adr + (SM_BL - SM_BH) + j * 16 * 144 + ks * 32);
                MMA_BF16(acc[0][2 * j],     ah0, bh);
                MMA_BF16(acc[1][2 * j],     ah1, bh);
                MMA_BF16(acc[0][2 * j + 1], ah0, bh + 2);
                MMA_BF16(acc[1][2 * j + 1], ah1, bh + 2);
                MMA_BF16(acc[0][2 * j],     al0, bh);
                MMA_BF16(acc[1][2 * j],     al1, bh);
                MMA_BF16(acc[0][2 * j + 1], al0, bh + 2);
                MMA_BF16(acc[1][2 * j + 1], al1, bh + 2);
                MMA_BF16(acc[0][2 * j],     ah0, bl);
                MMA_BF16(acc[1][2 * j],     ah1, bl);
                MMA_BF16(acc[0][2 * j + 1], ah0, bl + 2);
                MMA_BF16(acc[1][2 * j + 1], ah1, bl + 2);
            }
        }
    }

    // ---- epilogue: scale by dinv[row], write fp16 xwh ----
    uint32_t* xw = (uint32_t*)g_xwh;            // row stride 64 uint (half2)
    const int nb2 = wn * 32;                    // half2-base
    #pragma unroll
    for (int t = 0; t < 2; t++) {
        int r_lo = row0 + wm * 32 + t * 16 + (lane >> 2);
        int r_hi = r_lo + 8;
        float d_lo = (r_lo < N) ? g_dinv[r_lo] : 0.f;
        float d_hi = (r_hi < N) ? g_dinv[r_hi] : 0.f;
        #pragma unroll
        for (int nt = 0; nt < 8; nt++) {
            int ci = nb2 + nt * 4 + (lane & 3);
            if (r_lo < N) {
                __half2 p = __floats2half2_rn(acc[t][nt][0] * d_lo, acc[t][nt][1] * d_lo);
                xw[(size_t)r_lo * 64 + ci] = *(uint32_t*)&p;
            }
            if (r_hi < N) {
                __half2 p = __floats2half2_rn(acc[t][nt][2] * d_hi, acc[t][nt][3] * d_hi);
                xw[(size_t)r_hi * 64 + ci] = *(uint32_t*)&p;
            }
        }
    }
}

// ---------------------------------------------------------------------------
__device__ __forceinline__ void add_h4(float4& a, uint2 u) {
    float2 f0 = __half22float2(*(__half2*)&u.x);
    float2 f1 = __half22float2(*(__half2*)&u.y);
    a.x += f0.x; a.y += f0.y; a.z += f1.x; a.w += f1.y;
}

// 6) aggregation: one warp per node, fp16 gathers, fp32 accumulation.
__global__ void __launch_bounds__(256) agg_kernel(const float* __restrict__ b,
                                                  float* __restrict__ out, int N) {
    int warp = (blockIdx.x * blockDim.x + threadIdx.x) >> 5;
    int lane = threadIdx.x & 31;
    if (warp >= N) return;
    int node = warp;

    const uint2* xw = (const uint2*)g_xwh;      // row stride 32 uint2
    float4 acc = make_float4(0.f, 0.f, 0.f, 0.f);
    add_h4(acc, xw[(size_t)node * 32 + lane]);  // self-loop
    float4 bb = ((const float4*)b)[lane];

    int e   = g_rowptr[node];
    int end = g_rowptr[node + 1];
    for (; e + 4 <= end; e += 4) {
        int s0 = g_srcid[e],     s1 = g_srcid[e + 1];
        int s2 = g_srcid[e + 2], s3 = g_srcid[e + 3];
        uint2 u0 = xw[(size_t)s0 * 32 + lane];
        uint2 u1 = xw[(size_t)s1 * 32 + lane];
        uint2 u2 = xw[(size_t)s2 * 32 + lane];
        uint2 u3 = xw[(size_t)s3 * 32 + lane];
        add_h4(acc, u0); add_h4(acc, u1); add_h4(acc, u2); add_h4(acc, u3);
    }
    for (; e < end; e++)
        add_h4(acc, xw[(size_t)g_srcid[e] * 32 + lane]);

    float di = g_dinv[node];
    float4 o;
    o.x = fmaxf(fmaf(di, acc.x, bb.x), 0.f);
    o.y = fmaxf(fmaf(di, acc.y, bb.y), 0.f);
    o.z = fmaxf(fmaf(di, acc.z, bb.z), 0.f);
    o.w = fmaxf(fmaf(di, acc.w, bb.w), 0.f);
    ((float4*)out)[(size_t)node * 32 + lane] = o;
}

// ---------------------------------------------------------------------------
extern "C" void kernel_launch(void* const* d_in, const int* in_sizes, int n_in,
                              void* d_out, int out_size) {
    const float* x  = (const float*)d_in[0];
    const void*  ei = d_in[1];                 // [2, E] int32 or int64 (probed)
    const float* W  = (const float*)d_in[2];
    const float* b  = (const float*)d_in[3];
    float*       out = (float*)d_out;

    const int N = in_sizes[0] / 256;   // 40000
    const int E = in_sizes[1] / 2;     // 640000

    cudaFuncSetAttribute(gemm_kernel, cudaFuncAttributeMaxDynamicSharedMemorySize, SM_TOT);

    // Order chosen so the ncu sample slot (4th launch) captures the GEMM.
    init_kernel<<<(N + 255) / 256, 256>>>((const int*)ei, W, N);
    count_kernel<<<(E + 255) / 256, 256>>>(ei, E, N);
    scan_kernel<<<1, 1024>>>(N);
    gemm_kernel<<<(N + 127) / 128, 256, SM_TOT>>>(x, N);
    scatter_kernel<<<(E + 255) / 256, 256>>>(ei, E, N);
    agg_kernel<<<(N * 32 + 255) / 256, 256>>>(b, out, N);
}

// round 7
// speedup vs baseline: 1.8702x; 1.0476x over previous
#include <cuda_runtime.h>
#include <cuda_bf16.h>
#include <cuda_fp16.h>
#include <cstdint>

// Problem shape: N=40000 nodes, F_in=256, F_out=128, E=640000 edges.
static constexpr int MAXN = 40000;
static constexpr int MAXE = 640000;

// Scratch (allocation-free rule: __device__ globals)
__device__ int    g_is64;               // 1 if edge_index is int64, 0 if int32
__device__ __align__(16) int g_cnt[MAXN];   // in-degree; reused as scatter cursor
__device__ int    g_rowptr[MAXN + 1];   // CSR row pointers (by dst)
__device__ float  g_dinv[MAXN];         // rsqrt(deg+1)
__device__ int    g_srcid[MAXE];        // CSR column (source node) ids
__device__ __align__(16) __half g_xwh[MAXN * 128];  // fp16 dinv[i]*(x@W)[i]
// W^T split images: [n=128][k=256] bf16, hi and lo
__device__ __align__(16) __nv_bfloat16 g_wh[128 * 256];
__device__ __align__(16) __nv_bfloat16 g_wl[128 * 256];

// ---------------------------------------------------------------------------
__device__ __forceinline__ uint32_t smem_u32(const void* p) {
    uint32_t a;
    asm("{ .reg .u64 t; cvta.to.shared.u64 t, %1; cvt.u32.u64 %0, t; }" : "=r"(a) : "l"(p));
    return a;
}
#define LDSM_X4(r0, r1, r2, r3, adr)                                              \
    asm volatile("ldmatrix.sync.aligned.m8n8.x4.shared.b16 {%0,%1,%2,%3}, [%4];"  \
                 : "=r"(r0), "=r"(r1), "=r"(r2), "=r"(r3) : "r"(adr))
#define MMA_BF16(c, a, b)                                                         \
    asm volatile("mma.sync.aligned.m16n8k16.row.col.f32.bf16.bf16.f32 "           \
                 "{%0,%1,%2,%3}, {%4,%5,%6,%7}, {%8,%9}, {%0,%1,%2,%3};"          \
                 : "+f"((c)[0]), "+f"((c)[1]), "+f"((c)[2]), "+f"((c)[3])         \
                 : "r"((a)[0]), "r"((a)[1]), "r"((a)[2]), "r"((a)[3]),            \
                   "r"((b)[0]), "r"((b)[1]))

// ---------------------------------------------------------------------------
// 1) init: zero counters; block 0 probes index dtype; first 32768 threads
//    build W^T split-bf16 images.
__global__ void init_kernel(const int* __restrict__ ei32,
                            const float* __restrict__ W, int N) {
    int i = blockIdx.x * blockDim.x + threadIdx.x;
    if (i < N) g_cnt[i] = 0;
    if (i < 128 * 256) {
        int k = i & 255;
        int n = i >> 8;
        float v = W[(size_t)k * 128 + n];
        __nv_bfloat16 hi = __float2bfloat16_rn(v);
        __nv_bfloat16 lo = __float2bfloat16_rn(v - __bfloat162float(hi));
        g_wh[n * 256 + k] = hi;
        g_wl[n * 256 + k] = lo;
    }
    if (blockIdx.x == 0) {
        __shared__ int red[8];
        int tid = threadIdx.x;
        int acc = 0;
        for (int k = tid; k < 1024; k += 256)
            acc |= ei32[2 * k + 1];              // int64 high halves
        #pragma unroll
        for (int off = 16; off > 0; off >>= 1)
            acc |= __shfl_down_sync(0xFFFFFFFFu, acc, off);
        if ((tid & 31) == 0) red[tid >> 5] = acc;
        __syncthreads();
        if (tid == 0) {
            int r = 0;
            #pragma unroll
            for (int w = 0; w < 8; w++) r |= red[w];
            g_is64 = (r == 0) ? 1 : 0;
        }
    }
}

__device__ __forceinline__ int load_idx(const void* ei, long long i, int is64) {
    if (is64) return (int)((const long long*)ei)[i];
    return ((const int*)ei)[i];
}

// 2) histogram of dst
__global__ void count_kernel(const void* __restrict__ ei, int E, int N) {
    int e = blockIdx.x * blockDim.x + threadIdx.x;
    if (e < E) {
        int is64 = g_is64;
        unsigned d = (unsigned)load_idx(ei, (long long)E + e, is64);
        if (d < (unsigned)N) atomicAdd(&g_cnt[d], 1);
    }
}

// 3) exclusive scan of g_cnt -> g_rowptr; fused dinv. 4 elements/thread.
__global__ void __launch_bounds__(1024) scan_kernel(int N) {
    __shared__ int shw[32];
    __shared__ int carry;
    int tid = threadIdx.x, lane = tid & 31, warp = tid >> 5;
    if (tid == 0) { carry = 0; g_rowptr[0] = 0; }
    __syncthreads();
    for (int base = 0; base < N; base += 4096) {
        int i0 = base + tid * 4;
        int v[4];
        if (i0 + 3 < N) {
            int4 q = *(const int4*)&g_cnt[i0];
            v[0] = q.x; v[1] = q.y; v[2] = q.z; v[3] = q.w;
        } else {
            #pragma unroll
            for (int j = 0; j < 4; j++) v[j] = (i0 + j < N) ? g_cnt[i0 + j] : 0;
        }
        int tsum = v[0] + v[1] + v[2] + v[3];
        int s = tsum;
        #pragma unroll
        for (int off = 1; off < 32; off <<= 1) {
            int t = __shfl_up_sync(0xFFFFFFFFu, s, off);
            if (lane >= off) s += t;
        }
        if (lane == 31) shw[warp] = s;
        __syncthreads();
        if (warp == 0) {
            int ws = shw[lane];
            #pragma unroll
            for (int off = 1; off < 32; off <<= 1) {
                int t = __shfl_up_sync(0xFFFFFFFFu, ws, off);
                if (lane >= off) ws += t;
            }
            shw[lane] = ws;
        }
        __syncthreads();
        int run = (s - tsum) + (warp > 0 ? shw[warp - 1] : 0) + carry;
        #pragma unroll
        for (int j = 0; j < 4; j++) {
            run += v[j];
            if (i0 + j < N) {
                g_rowptr[i0 + j + 1] = run;
                g_dinv[i0 + j] = rsqrtf((float)v[j] + 1.0f);
            }
        }
        __syncthreads();
        if (tid == 0) carry += shw[31];
        __syncthreads();
    }
}

// 4) scatter edge source ids into CSR slots (g_cnt doubles as down-cursor)
__global__ void scatter_kernel(const void* __restrict__ ei, int E, int N) {
    int e = blockIdx.x * blockDim.x + threadIdx.x;
    if (e < E) {
        int is64 = g_is64;
        unsigned d = (unsigned)load_idx(ei, (long long)E + e, is64);
        unsigned s = (unsigned)load_idx(ei, e, is64);
        if (d < (unsigned)N && s < (unsigned)N) {
            int v = atomicSub(&g_cnt[d], 1);          // old value in [1..deg]
            g_srcid[g_rowptr[d] + v - 1] = (int)s;
        }
    }
}

// ---------------------------------------------------------------------------
// 5) GEMM via mma.sync bf16 split: xwh[i,:] = fp16( dinv[i] * (x[i,:] @ W) )
//    CTA 128Mx128N, 16 warps (4Mx4N), warp 32Mx32N; K chunks of 64.
//    512 threads, <=64 regs -> 2 CTAs/SM = 32 warps/SM (latency hiding).
static constexpr int SM_AH  = 0;
static constexpr int SM_AL  = 18432;
static constexpr int SM_BH  = 36864;
static constexpr int SM_BL  = 55296;
static constexpr int SM_TOT = 73728;

__global__ void __launch_bounds__(512, 2)
gemm_kernel(const float* __restrict__ x, int N) {
    extern __shared__ unsigned char smc[];
    const uint32_t sm = smem_u32(smc);
    const int tid  = threadIdx.x;
    const int lane = tid & 31;
    const int wid  = tid >> 5;
    const int wm   = wid >> 2;          // 0..3 -> M offset wm*32
    const int wn   = wid & 3;           // 0..3 -> N offset wn*32
    const int row0 = blockIdx.x * 128;

    const float4* X4 = (const float4*)x;          // row stride 64 float4
    const uint4*  WH = (const uint4*)g_wh;        // row = 32 uint4
    const uint4*  WL = (const uint4*)g_wl;

    float acc[2][4][4];
    #pragma unroll
    for (int t = 0; t < 2; t++)
        #pragma unroll
        for (int nt = 0; nt < 4; nt++)
            #pragma unroll
            for (int j = 0; j < 4; j++) acc[t][nt][j] = 0.f;

    const int m = tid >> 2;             // producer row 0..127
    const int h = tid & 3;              // k-quarter (16 floats) within chunk
    const int rr = min(row0 + m, N - 1);

    const uint32_t a_adr0 = sm + SM_AH + (wm * 32 + 0  + (lane & 15)) * 144 + ((lane >> 4) << 4);
    const uint32_t a_adr1 = sm + SM_AH + (wm * 32 + 16 + (lane & 15)) * 144 + ((lane >> 4) << 4);
    const uint32_t b_row  = (uint32_t)(wn * 32 + ((lane >> 4) << 3) + (lane & 7));
    const uint32_t b_koff = (uint32_t)(((lane >> 3) & 1) << 4);
    const uint32_t b_adr  = sm + SM_BH + b_row * 144 + b_koff;

    for (int c = 0; c < 4; c++) {
        if (c > 0) __syncthreads();     // previous compute done before overwrite
        // ---- A: load 4 float4 -> split bf16 -> STS (2x uint4 hi, 2x lo) ----
        #pragma unroll
        for (int p = 0; p < 2; p++) {
            float4 f0 = X4[(size_t)rr * 64 + c * 16 + h * 4 + p * 2];
            float4 f1 = X4[(size_t)rr * 64 + c * 16 + h * 4 + p * 2 + 1];
            __nv_bfloat162 h0 = __floats2bfloat162_rn(f0.x, f0.y);
            __nv_bfloat162 h1 = __floats2bfloat162_rn(f0.z, f0.w);
            __nv_bfloat162 h2 = __floats2bfloat162_rn(f1.x, f1.y);
            __nv_bfloat162 h3 = __floats2bfloat162_rn(f1.z, f1.w);
            float2 a0 = __bfloat1622float2(h0);
            float2 a1 = __bfloat1622float2(h1);
            float2 a2 = __bfloat1622float2(h2);
            float2 a3 = __bfloat1622float2(h3);
            __nv_bfloat162 l0 = __floats2bfloat162_rn(f0.x - a0.x, f0.y - a0.y);
            __nv_bfloat162 l1 = __floats2bfloat162_rn(f0.z - a1.x, f0.w - a1.y);
            __nv_bfloat162 l2 = __floats2bfloat162_rn(f1.x - a2.x, f1.y - a2.y);
            __nv_bfloat162 l3 = __floats2bfloat162_rn(f1.z - a3.x, f1.w - a3.y);
            uint32_t off = (uint32_t)(m * 144 + h * 32 + p * 16);
            *(uint4*)(smc + SM_AH + off) = make_uint4(
                *(uint32_t*)&h0, *(uint32_t*)&h1, *(uint32_t*)&h2, *(uint32_t*)&h3);
            *(uint4*)(smc + SM_AL + off) = make_uint4(
                *(uint32_t*)&l0, *(uint32_t*)&l1, *(uint32_t*)&l2, *(uint32_t*)&l3);
        }
        // ---- B chunk copy (hi/lo), 2 uint4 each per thread (L2-resident) ----
        #pragma unroll
        for (int it = 0; it < 2; it++) {
            int idx = tid + it * 512;          // 0..1023
            int n   = idx >> 3;
            int kq  = idx & 7;
            uint32_t dst = (uint32_t)(n * 144 + kq * 16);
            *(uint4*)(smc + SM_BH + dst) = WH[n * 32 + c * 8 + kq];
            *(uint4*)(smc + SM_BL + dst) = WL[n * 32 + c * 8 + kq];
        }
        __syncthreads();

        // ---- compute: 4 k16 steps ----
        #pragma unroll
        for (int ks = 0; ks < 4; ks++) {
            uint32_t ah0[4], ah1[4], al0[4], al1[4];
            LDSM_X4(ah0[0], ah0[1], ah0[2], ah0[3], a_adr0 + ks * 32);
            LDSM_X4(ah1[0], ah1[1], ah1[2], ah1[3], a_adr1 + ks * 32);
            LDSM_X4(al0[0], al0[1], al0[2], al0[3], a_adr0 + (SM_AL - SM_AH) + ks * 32);
            LDSM_X4(al1[0], al1[1], al1[2], al1[3], a_adr1 + (SM_AL - SM_AH) + ks * 32);
            #pragma unroll
            for (int j = 0; j < 2; j++) {      // 2 n16-groups
                uint32_t bh[4], bl[4];
                LDSM_X4(bh[0], bh[1], bh[2], bh[3], b_adr + j * 16 * 144 + ks * 32);
                LDSM_X4(bl[0], bl[1], bl[2], bl[3],
                        b_adr + (SM_BL - SM_BH) + j * 16 * 144 + ks * 32);
                MMA_BF16(acc[0][2 * j],     ah0, bh);
                MMA_BF16(acc[1][2 * j],     ah1, bh);
                MMA_BF16(acc[0][2 * j + 1], ah0, bh + 2);
                MMA_BF16(acc[1][2 * j + 1], ah1, bh + 2);
                MMA_BF16(acc[0][2 * j],     al0, bh);
                MMA_BF16(acc[1][2 * j],     al1, bh);
                MMA_BF16(acc[0][2 * j + 1], al0, bh + 2);
                MMA_BF16(acc[1][2 * j + 1], al1, bh + 2);
                MMA_BF16(acc[0][2 * j],     ah0, bl);
                MMA_BF16(acc[1][2 * j],     ah1, bl);
                MMA_BF16(acc[0][2 * j + 1], ah0, bl + 2);
                MMA_BF16(acc[1][2 * j + 1], ah1, bl + 2);
            }
        }
    }

    // ---- epilogue: scale by dinv[row], write fp16 xwh ----
    uint32_t* xw = (uint32_t*)g_xwh;            // row stride 64 uint (half2)
    const int nb2 = wn * 16;                    // half2-base
    #pragma unroll
    for (int t = 0; t < 2; t++) {
        int r_lo = row0 + wm * 32 + t * 16 + (lane >> 2);
        int r_hi = r_lo + 8;
        float d_lo = (r_lo < N) ? g_dinv[r_lo] : 0.f;
        float d_hi = (r_hi < N) ? g_dinv[r_hi] : 0.f;
        #pragma unroll
        for (int nt = 0; nt < 4; nt++) {
            int ci = nb2 + nt * 4 + (lane & 3);
            if (r_lo < N) {
                __half2 p = __floats2half2_rn(acc[t][nt][0] * d_lo, acc[t][nt][1] * d_lo);
                xw[(size_t)r_lo * 64 + ci] = *(uint32_t*)&p;
            }
            if (r_hi < N) {
                __half2 p = __floats2half2_rn(acc[t][nt][2] * d_hi, acc[t][nt][3] * d_hi);
                xw[(size_t)r_hi * 64 + ci] = *(uint32_t*)&p;
            }
        }
    }
}

// ---------------------------------------------------------------------------
__device__ __forceinline__ void add_h4(float4& a, uint2 u) {
    float2 f0 = __half22float2(*(__half2*)&u.x);
    float2 f1 = __half22float2(*(__half2*)&u.y);
    a.x += f0.x; a.y += f0.y; a.z += f1.x; a.w += f1.y;
}

// 6) aggregation: one warp per node, fp16 gathers, fp32 accumulation.
__global__ void __launch_bounds__(256) agg_kernel(const float* __restrict__ b,
                                                  float* __restrict__ out, int N) {
    int warp = (blockIdx.x * blockDim.x + threadIdx.x) >> 5;
    int lane = threadIdx.x & 31;
    if (warp >= N) return;
    int node = warp;

    const uint2* xw = (const uint2*)g_xwh;      // row stride 32 uint2
    float4 acc = make_float4(0.f, 0.f, 0.f, 0.f);
    add_h4(acc, xw[(size_t)node * 32 + lane]);  // self-loop
    float4 bb = ((const float4*)b)[lane];

    int e   = g_rowptr[node];
    int end = g_rowptr[node + 1];
    for (; e + 4 <= end; e += 4) {
        int s0 = g_srcid[e],     s1 = g_srcid[e + 1];
        int s2 = g_srcid[e + 2], s3 = g_srcid[e + 3];
        uint2 u0 = xw[(size_t)s0 * 32 + lane];
        uint2 u1 = xw[(size_t)s1 * 32 + lane];
        uint2 u2 = xw[(size_t)s2 * 32 + lane];
        uint2 u3 = xw[(size_t)s3 * 32 + lane];
        add_h4(acc, u0); add_h4(acc, u1); add_h4(acc, u2); add_h4(acc, u3);
    }
    for (; e < end; e++)
        add_h4(acc, xw[(size_t)g_srcid[e] * 32 + lane]);

    float di = g_dinv[node];
    float4 o;
    o.x = fmaxf(fmaf(di, acc.x, bb.x), 0.f);
    o.y = fmaxf(fmaf(di, acc.y, bb.y), 0.f);
    o.z = fmaxf(fmaf(di, acc.z, bb.z), 0.f);
    o.w = fmaxf(fmaf(di, acc.w, bb.w), 0.f);
    ((float4*)out)[(size_t)node * 32 + lane] = o;
}

// ---------------------------------------------------------------------------
extern "C" void kernel_launch(void* const* d_in, const int* in_sizes, int n_in,
                              void* d_out, int out_size) {
    const float* x  = (const float*)d_in[0];
    const void*  ei = d_in[1];                 // [2, E] int32 or int64 (probed)
    const float* W  = (const float*)d_in[2];
    const float* b  = (const float*)d_in[3];
    float*       out = (float*)d_out;

    const int N = in_sizes[0] / 256;   // 40000
    const int E = in_sizes[1] / 2;     // 640000

    cudaFuncSetAttribute(gemm_kernel, cudaFuncAttributeMaxDynamicSharedMemorySize, SM_TOT);

    // Order chosen so the ncu sample slot (4th launch) captures the GEMM.
    init_kernel<<<(N + 255) / 256, 256>>>((const int*)ei, W, N);
    count_kernel<<<(E + 255) / 256, 256>>>(ei, E, N);
    scan_kernel<<<1, 1024>>>(N);
    gemm_kernel<<<(N + 127) / 128, 512, SM_TOT>>>(x, N);
    scatter_kernel<<<(E + 255) / 256, 256>>>(ei, E, N);
    agg_kernel<<<(N * 32 + 255) / 256, 256>>>(b, out, N);
}

// round 8
// speedup vs baseline: 1.9805x; 1.0590x over previous
#include <cuda_runtime.h>
#include <cuda_bf16.h>
#include <cuda_fp16.h>
#include <cstdint>

// Problem shape: N=40000 nodes, F_in=256, F_out=128, E=640000 edges.
static constexpr int MAXN = 40000;
static constexpr int MAXE = 640000;

// Scratch (allocation-free rule: __device__ globals)
__device__ int    g_is64;               // 1 if edge_index is int64, 0 if int32
__device__ __align__(16) int g_cnt[MAXN];   // in-degree; reused as scatter cursor
__device__ int    g_rowptr[MAXN + 1];   // CSR row pointers (by dst)
__device__ float  g_dinv[MAXN];         // rsqrt(deg+1)
__device__ int    g_srcid[MAXE];        // CSR column (source node) ids
__device__ __align__(16) __half g_xwh[MAXN * 128];  // fp16 dinv[i]*(x@W)[i]
// W^T split images: [n=128][k=256] fp16, hi and lo
__device__ __align__(16) __half g_wh[128 * 256];
__device__ __align__(16) __half g_wl[128 * 256];

// ---------------------------------------------------------------------------
__device__ __forceinline__ uint32_t smem_u32(const void* p) {
    uint32_t a;
    asm("{ .reg .u64 t; cvta.to.shared.u64 t, %1; cvt.u32.u64 %0, t; }" : "=r"(a) : "l"(p));
    return a;
}
#define LDSM_X4(r0, r1, r2, r3, adr)                                              \
    asm volatile("ldmatrix.sync.aligned.m8n8.x4.shared.b16 {%0,%1,%2,%3}, [%4];"  \
                 : "=r"(r0), "=r"(r1), "=r"(r2), "=r"(r3) : "r"(adr))
#define MMA_F16(c, a, b)                                                          \
    asm volatile("mma.sync.aligned.m16n8k16.row.col.f32.f16.f16.f32 "             \
                 "{%0,%1,%2,%3}, {%4,%5,%6,%7}, {%8,%9}, {%0,%1,%2,%3};"          \
                 : "+f"((c)[0]), "+f"((c)[1]), "+f"((c)[2]), "+f"((c)[3])         \
                 : "r"((a)[0]), "r"((a)[1]), "r"((a)[2]), "r"((a)[3]),            \
                   "r"((b)[0]), "r"((b)[1]))

// ---------------------------------------------------------------------------
// 1) init: zero counters; block 0 probes index dtype; first 32768 threads
//    build W^T split-fp16 images.
__global__ void init_kernel(const int* __restrict__ ei32,
                            const float* __restrict__ W, int N) {
    int i = blockIdx.x * blockDim.x + threadIdx.x;
    if (i < N) g_cnt[i] = 0;
    if (i < 128 * 256) {
        int k = i & 255;
        int n = i >> 8;
        float v = W[(size_t)k * 128 + n];
        __half hi = __float2half_rn(v);
        __half lo = __float2half_rn(v - __half2float(hi));
        g_wh[n * 256 + k] = hi;
        g_wl[n * 256 + k] = lo;
    }
    if (blockIdx.x == 0) {
        __shared__ int red[8];
        int tid = threadIdx.x;
        int acc = 0;
        for (int k = tid; k < 1024; k += 256)
            acc |= ei32[2 * k + 1];              // int64 high halves
        #pragma unroll
        for (int off = 16; off > 0; off >>= 1)
            acc |= __shfl_down_sync(0xFFFFFFFFu, acc, off);
        if ((tid & 31) == 0) red[tid >> 5] = acc;
        __syncthreads();
        if (tid == 0) {
            int r = 0;
            #pragma unroll
            for (int w = 0; w < 8; w++) r |= red[w];
            g_is64 = (r == 0) ? 1 : 0;
        }
    }
}

__device__ __forceinline__ int load_idx(const void* ei, long long i, int is64) {
    if (is64) return (int)((const long long*)ei)[i];
    return ((const int*)ei)[i];
}

// 2) histogram of dst
__global__ void count_kernel(const void* __restrict__ ei, int E, int N) {
    int e = blockIdx.x * blockDim.x + threadIdx.x;
    if (e < E) {
        int is64 = g_is64;
        unsigned d = (unsigned)load_idx(ei, (long long)E + e, is64);
        if (d < (unsigned)N) atomicAdd(&g_cnt[d], 1);
    }
}

// 3) exclusive scan of g_cnt -> g_rowptr; fused dinv. 4 elements/thread.
__global__ void __launch_bounds__(1024) scan_kernel(int N) {
    __shared__ int shw[32];
    __shared__ int carry;
    int tid = threadIdx.x, lane = tid & 31, warp = tid >> 5;
    if (tid == 0) { carry = 0; g_rowptr[0] = 0; }
    __syncthreads();
    for (int base = 0; base < N; base += 4096) {
        int i0 = base + tid * 4;
        int v[4];
        if (i0 + 3 < N) {
            int4 q = *(const int4*)&g_cnt[i0];
            v[0] = q.x; v[1] = q.y; v[2] = q.z; v[3] = q.w;
        } else {
            #pragma unroll
            for (int j = 0; j < 4; j++) v[j] = (i0 + j < N) ? g_cnt[i0 + j] : 0;
        }
        int tsum = v[0] + v[1] + v[2] + v[3];
        int s = tsum;
        #pragma unroll
        for (int off = 1; off < 32; off <<= 1) {
            int t = __shfl_up_sync(0xFFFFFFFFu, s, off);
            if (lane >= off) s += t;
        }
        if (lane == 31) shw[warp] = s;
        __syncthreads();
        if (warp == 0) {
            int ws = shw[lane];
            #pragma unroll
            for (int off = 1; off < 32; off <<= 1) {
                int t = __shfl_up_sync(0xFFFFFFFFu, ws, off);
                if (lane >= off) ws += t;
            }
            shw[lane] = ws;
        }
        __syncthreads();
        int run = (s - tsum) + (warp > 0 ? shw[warp - 1] : 0) + carry;
        #pragma unroll
        for (int j = 0; j < 4; j++) {
            run += v[j];
            if (i0 + j < N) {
                g_rowptr[i0 + j + 1] = run;
                g_dinv[i0 + j] = rsqrtf((float)v[j] + 1.0f);
            }
        }
        __syncthreads();
        if (tid == 0) carry += shw[31];
        __syncthreads();
    }
}

// 4) scatter edge source ids into CSR slots (g_cnt doubles as down-cursor)
__global__ void scatter_kernel(const void* __restrict__ ei, int E, int N) {
    int e = blockIdx.x * blockDim.x + threadIdx.x;
    if (e < E) {
        int is64 = g_is64;
        unsigned d = (unsigned)load_idx(ei, (long long)E + e, is64);
        unsigned s = (unsigned)load_idx(ei, e, is64);
        if (d < (unsigned)N && s < (unsigned)N) {
            int v = atomicSub(&g_cnt[d], 1);          // old value in [1..deg]
            g_srcid[g_rowptr[d] + v - 1] = (int)s;
        }
    }
}

// ---------------------------------------------------------------------------
// 5) GEMM via mma.sync fp16: xwh[i,:] = fp16( dinv[i] * (x[i,:] @ W) )
//    A = fp16(x) (1 image); W = Wh + Wl fp16 split -> 2 MMA terms per step.
//    CTA 128Mx128N, 16 warps (4Mx4N), warp 32Mx32N; K chunks of 64.
static constexpr int SM_AH  = 0;
static constexpr int SM_BH  = 18432;
static constexpr int SM_BL  = 36864;
static constexpr int SM_TOT = 55296;

__global__ void __launch_bounds__(512, 2)
gemm_kernel(const float* __restrict__ x, int N) {
    extern __shared__ unsigned char smc[];
    const uint32_t sm = smem_u32(smc);
    const int tid  = threadIdx.x;
    const int lane = tid & 31;
    const int wid  = tid >> 5;
    const int wm   = wid >> 2;          // 0..3 -> M offset wm*32
    const int wn   = wid & 3;           // 0..3 -> N offset wn*32
    const int row0 = blockIdx.x * 128;

    const float4* X4 = (const float4*)x;          // row stride 64 float4
    const uint4*  WH = (const uint4*)g_wh;        // row = 32 uint4
    const uint4*  WL = (const uint4*)g_wl;

    float acc[2][4][4];
    #pragma unroll
    for (int t = 0; t < 2; t++)
        #pragma unroll
        for (int nt = 0; nt < 4; nt++)
            #pragma unroll
            for (int j = 0; j < 4; j++) acc[t][nt][j] = 0.f;

    const int m = tid >> 2;             // producer row 0..127
    const int h = tid & 3;              // k-quarter (16 floats) within chunk
    const int rr = min(row0 + m, N - 1);

    const uint32_t a_adr0 = sm + SM_AH + (wm * 32 + 0  + (lane & 15)) * 144 + ((lane >> 4) << 4);
    const uint32_t a_adr1 = sm + SM_AH + (wm * 32 + 16 + (lane & 15)) * 144 + ((lane >> 4) << 4);
    const uint32_t b_row  = (uint32_t)(wn * 32 + ((lane >> 4) << 3) + (lane & 7));
    const uint32_t b_koff = (uint32_t)(((lane >> 3) & 1) << 4);
    const uint32_t b_adr  = sm + SM_BH + b_row * 144 + b_koff;

    for (int c = 0; c < 4; c++) {
        if (c > 0) __syncthreads();     // previous compute done before overwrite
        // ---- A: load 4 float4 -> fp16 -> STS (2x uint4) ----
        #pragma unroll
        for (int p = 0; p < 2; p++) {
            float4 f0 = X4[(size_t)rr * 64 + c * 16 + h * 4 + p * 2];
            float4 f1 = X4[(size_t)rr * 64 + c * 16 + h * 4 + p * 2 + 1];
            __half2 h0 = __floats2half2_rn(f0.x, f0.y);
            __half2 h1 = __floats2half2_rn(f0.z, f0.w);
            __half2 h2 = __floats2half2_rn(f1.x, f1.y);
            __half2 h3 = __floats2half2_rn(f1.z, f1.w);
            uint32_t off = (uint32_t)(m * 144 + h * 32 + p * 16);
            *(uint4*)(smc + SM_AH + off) = make_uint4(
                *(uint32_t*)&h0, *(uint32_t*)&h1, *(uint32_t*)&h2, *(uint32_t*)&h3);
        }
        // ---- B chunk copy (hi/lo), 2 uint4 each per thread (L2-resident) ----
        #pragma unroll
        for (int it = 0; it < 2; it++) {
            int idx = tid + it * 512;          // 0..1023
            int n   = idx >> 3;
            int kq  = idx & 7;
            uint32_t dst = (uint32_t)(n * 144 + kq * 16);
            *(uint4*)(smc + SM_BH + dst) = WH[n * 32 + c * 8 + kq];
            *(uint4*)(smc + SM_BL + dst) = WL[n * 32 + c * 8 + kq];
        }
        __syncthreads();

        // ---- compute: 4 k16 steps, 2 MMA terms (A*Bh + A*Bl) ----
        #pragma unroll
        for (int ks = 0; ks < 4; ks++) {
            uint32_t ah0[4], ah1[4];
            LDSM_X4(ah0[0], ah0[1], ah0[2], ah0[3], a_adr0 + ks * 32);
            LDSM_X4(ah1[0], ah1[1], ah1[2], ah1[3], a_adr1 + ks * 32);
            #pragma unroll
            for (int j = 0; j < 2; j++) {      // 2 n16-groups
                uint32_t bh[4], bl[4];
                LDSM_X4(bh[0], bh[1], bh[2], bh[3], b_adr + j * 16 * 144 + ks * 32);
                LDSM_X4(bl[0], bl[1], bl[2], bl[3],
                        b_adr + (SM_BL - SM_BH) + j * 16 * 144 + ks * 32);
                MMA_F16(acc[0][2 * j],     ah0, bh);
                MMA_F16(acc[1][2 * j],     ah1, bh);
                MMA_F16(acc[0][2 * j + 1], ah0, bh + 2);
                MMA_F16(acc[1][2 * j + 1], ah1, bh + 2);
                MMA_F16(acc[0][2 * j],     ah0, bl);
                MMA_F16(acc[1][2 * j],     ah1, bl);
                MMA_F16(acc[0][2 * j + 1], ah0, bl + 2);
                MMA_F16(acc[1][2 * j + 1], ah1, bl + 2);
            }
        }
    }

    // ---- epilogue: scale by dinv[row], write fp16 xwh ----
    uint32_t* xw = (uint32_t*)g_xwh;            // row stride 64 uint (half2)
    const int nb2 = wn * 16;                    // half2-base
    #pragma unroll
    for (int t = 0; t < 2; t++) {
        int r_lo = row0 + wm * 32 + t * 16 + (lane >> 2);
        int r_hi = r_lo + 8;
        float d_lo = (r_lo < N) ? g_dinv[r_lo] : 0.f;
        float d_hi = (r_hi < N) ? g_dinv[r_hi] : 0.f;
        #pragma unroll
        for (int nt = 0; nt < 4; nt++) {
            int ci = nb2 + nt * 4 + (lane & 3);
            if (r_lo < N) {
                __half2 p = __floats2half2_rn(acc[t][nt][0] * d_lo, acc[t][nt][1] * d_lo);
                xw[(size_t)r_lo * 64 + ci] = *(uint32_t*)&p;
            }
            if (r_hi < N) {
                __half2 p = __floats2half2_rn(acc[t][nt][2] * d_hi, acc[t][nt][3] * d_hi);
                xw[(size_t)r_hi * 64 + ci] = *(uint32_t*)&p;
            }
        }
    }
}

// ---------------------------------------------------------------------------
__device__ __forceinline__ void add_h4(float4& a, uint2 u) {
    float2 f0 = __half22float2(*(__half2*)&u.x);
    float2 f1 = __half22float2(*(__half2*)&u.y);
    a.x += f0.x; a.y += f0.y; a.z += f1.x; a.w += f1.y;
}

// 6) aggregation: one warp per node, fp16 gathers, fp32 accumulation.
__global__ void __launch_bounds__(256) agg_kernel(const float* __restrict__ b,
                                                  float* __restrict__ out, int N) {
    int warp = (blockIdx.x * blockDim.x + threadIdx.x) >> 5;
    int lane = threadIdx.x & 31;
    if (warp >= N) return;
    int node = warp;

    const uint2* xw = (const uint2*)g_xwh;      // row stride 32 uint2
    float4 acc = make_float4(0.f, 0.f, 0.f, 0.f);
    add_h4(acc, xw[(size_t)node * 32 + lane]);  // self-loop
    float4 bb = ((const float4*)b)[lane];

    int e   = g_rowptr[node];
    int end = g_rowptr[node + 1];
    for (; e + 4 <= end; e += 4) {
        int s0 = g_srcid[e],     s1 = g_srcid[e + 1];
        int s2 = g_srcid[e + 2], s3 = g_srcid[e + 3];
        uint2 u0 = xw[(size_t)s0 * 32 + lane];
        uint2 u1 = xw[(size_t)s1 * 32 + lane];
        uint2 u2 = xw[(size_t)s2 * 32 + lane];
        uint2 u3 = xw[(size_t)s3 * 32 + lane];
        add_h4(acc, u0); add_h4(acc, u1); add_h4(acc, u2); add_h4(acc, u3);
    }
    for (; e < end; e++)
        add_h4(acc, xw[(size_t)g_srcid[e] * 32 + lane]);

    float di = g_dinv[node];
    float4 o;
    o.x = fmaxf(fmaf(di, acc.x, bb.x), 0.f);
    o.y = fmaxf(fmaf(di, acc.y, bb.y), 0.f);
    o.z = fmaxf(fmaf(di, acc.z, bb.z), 0.f);
    o.w = fmaxf(fmaf(di, acc.w, bb.w), 0.f);
    ((float4*)out)[(size_t)node * 32 + lane] = o;
}

// ---------------------------------------------------------------------------
extern "C" void kernel_launch(void* const* d_in, const int* in_sizes, int n_in,
                              void* d_out, int out_size) {
    const float* x  = (const float*)d_in[0];
    const void*  ei = d_in[1];                 // [2, E] int32 or int64 (probed)
    const float* W  = (const float*)d_in[2];
    const float* b  = (const float*)d_in[3];
    float*       out = (float*)d_out;

    const int N = in_sizes[0] / 256;   // 40000
    const int E = in_sizes[1] / 2;     // 640000

    cudaFuncSetAttribute(gemm_kernel, cudaFuncAttributeMaxDynamicSharedMemorySize, SM_TOT);

    // Order chosen so the ncu sample slot (4th launch) captures the GEMM.
    init_kernel<<<(N + 255) / 256, 256>>>((const int*)ei, W, N);
    count_kernel<<<(E + 255) / 256, 256>>>(ei, E, N);
    scan_kernel<<<1, 1024>>>(N);
    gemm_kernel<<<(N + 127) / 128, 512, SM_TOT>>>(x, N);
    scatter_kernel<<<(E + 255) / 256, 256>>>(ei, E, N);
    agg_kernel<<<(N * 32 + 255) / 256, 256>>>(b, out, N);
}

// round 9
// speedup vs baseline: 2.1462x; 1.0836x over previous
#include <cuda_runtime.h>
#include <cuda_bf16.h>
#include <cuda_fp16.h>
#include <cstdint>

// Problem shape: N=40000 nodes, F_in=256, F_out=128, E=640000 edges.
static constexpr int MAXN = 40000;
static constexpr int MAXE = 640000;

// Scratch (allocation-free rule: __device__ globals)
__device__ int    g_is64;               // 1 if edge_index is int64, 0 if int32
__device__ __align__(16) int g_cnt[MAXN];   // in-degree; reused as scatter cursor
__device__ int    g_rowptr[MAXN + 1];   // CSR row pointers (by dst)
__device__ float  g_dinv[MAXN];         // rsqrt(deg+1)
__device__ int    g_srcid[MAXE];        // CSR column (source node) ids
__device__ __align__(16) __half g_xwh[MAXN * 128];  // fp16 dinv[i]*(x@W)[i]
// W^T image: [n=128][k=256] fp16
__device__ __align__(16) __half g_wh[128 * 256];

// ---------------------------------------------------------------------------
__device__ __forceinline__ uint32_t smem_u32(const void* p) {
    uint32_t a;
    asm("{ .reg .u64 t; cvta.to.shared.u64 t, %1; cvt.u32.u64 %0, t; }" : "=r"(a) : "l"(p));
    return a;
}
#define LDSM_X4(r0, r1, r2, r3, adr)                                              \
    asm volatile("ldmatrix.sync.aligned.m8n8.x4.shared.b16 {%0,%1,%2,%3}, [%4];"  \
                 : "=r"(r0), "=r"(r1), "=r"(r2), "=r"(r3) : "r"(adr))
#define MMA_F16(c, a, b)                                                          \
    asm volatile("mma.sync.aligned.m16n8k16.row.col.f32.f16.f16.f32 "             \
                 "{%0,%1,%2,%3}, {%4,%5,%6,%7}, {%8,%9}, {%0,%1,%2,%3};"          \
                 : "+f"((c)[0]), "+f"((c)[1]), "+f"((c)[2]), "+f"((c)[3])         \
                 : "r"((a)[0]), "r"((a)[1]), "r"((a)[2]), "r"((a)[3]),            \
                   "r"((b)[0]), "r"((b)[1]))

// ---------------------------------------------------------------------------
// 1) init: zero counters; block 0 probes index dtype; first 32768 threads
//    build the W^T fp16 image.
__global__ void init_kernel(const int* __restrict__ ei32,
                            const float* __restrict__ W, int N) {
    int i = blockIdx.x * blockDim.x + threadIdx.x;
    if (i < N) g_cnt[i] = 0;
    if (i < 128 * 256) {
        int k = i & 255;
        int n = i >> 8;
        g_wh[n * 256 + k] = __float2half_rn(W[(size_t)k * 128 + n]);
    }
    if (blockIdx.x == 0) {
        __shared__ int red[8];
        int tid = threadIdx.x;
        int acc = 0;
        for (int k = tid; k < 1024; k += 256)
            acc |= ei32[2 * k + 1];              // int64 high halves
        #pragma unroll
        for (int off = 16; off > 0; off >>= 1)
            acc |= __shfl_down_sync(0xFFFFFFFFu, acc, off);
        if ((tid & 31) == 0) red[tid >> 5] = acc;
        __syncthreads();
        if (tid == 0) {
            int r = 0;
            #pragma unroll
            for (int w = 0; w < 8; w++) r |= red[w];
            g_is64 = (r == 0) ? 1 : 0;
        }
    }
}

__device__ __forceinline__ int load_idx(const void* ei, long long i, int is64) {
    if (is64) return (int)((const long long*)ei)[i];
    return ((const int*)ei)[i];
}

// 2) histogram of dst
__global__ void count_kernel(const void* __restrict__ ei, int E, int N) {
    int e = blockIdx.x * blockDim.x + threadIdx.x;
    if (e < E) {
        int is64 = g_is64;
        unsigned d = (unsigned)load_idx(ei, (long long)E + e, is64);
        if (d < (unsigned)N) atomicAdd(&g_cnt[d], 1);
    }
}

// 3) exclusive scan of g_cnt -> g_rowptr; fused dinv. 4 elements/thread.
__global__ void __launch_bounds__(1024) scan_kernel(int N) {
    __shared__ int shw[32];
    __shared__ int carry;
    int tid = threadIdx.x, lane = tid & 31, warp = tid >> 5;
    if (tid == 0) { carry = 0; g_rowptr[0] = 0; }
    __syncthreads();
    for (int base = 0; base < N; base += 4096) {
        int i0 = base + tid * 4;
        int v[4];
        if (i0 + 3 < N) {
            int4 q = *(const int4*)&g_cnt[i0];
            v[0] = q.x; v[1] = q.y; v[2] = q.z; v[3] = q.w;
        } else {
            #pragma unroll
            for (int j = 0; j < 4; j++) v[j] = (i0 + j < N) ? g_cnt[i0 + j] : 0;
        }
        int tsum = v[0] + v[1] + v[2] + v[3];
        int s = tsum;
        #pragma unroll
        for (int off = 1; off < 32; off <<= 1) {
            int t = __shfl_up_sync(0xFFFFFFFFu, s, off);
            if (lane >= off) s += t;
        }
        if (lane == 31) shw[warp] = s;
        __syncthreads();
        if (warp == 0) {
            int ws = shw[lane];
            #pragma unroll
            for (int off = 1; off < 32; off <<= 1) {
                int t = __shfl_up_sync(0xFFFFFFFFu, ws, off);
                if (lane >= off) ws += t;
            }
            shw[lane] = ws;
        }
        __syncthreads();
        int run = (s - tsum) + (warp > 0 ? shw[warp - 1] : 0) + carry;
        #pragma unroll
        for (int j = 0; j < 4; j++) {
            run += v[j];
            if (i0 + j < N) {
                g_rowptr[i0 + j + 1] = run;
                g_dinv[i0 + j] = rsqrtf((float)v[j] + 1.0f);
            }
        }
        __syncthreads();
        if (tid == 0) carry += shw[31];
        __syncthreads();
    }
}

// 4) scatter edge source ids into CSR slots (g_cnt doubles as down-cursor)
__global__ void scatter_kernel(const void* __restrict__ ei, int E, int N) {
    int e = blockIdx.x * blockDim.x + threadIdx.x;
    if (e < E) {
        int is64 = g_is64;
        unsigned d = (unsigned)load_idx(ei, (long long)E + e, is64);
        unsigned s = (unsigned)load_idx(ei, e, is64);
        if (d < (unsigned)N && s < (unsigned)N) {
            int v = atomicSub(&g_cnt[d], 1);          // old value in [1..deg]
            g_srcid[g_rowptr[d] + v - 1] = (int)s;
        }
    }
}

// ---------------------------------------------------------------------------
// 5) GEMM via mma.sync fp16: xwh[i,:] = fp16( dinv[i] * (x[i,:] @ W) )
//    Single term: A = fp16(x), B = fp16(W).
//    CTA 128Mx128N, 16 warps (4Mx4N), warp 32Mx32N; K chunks of 64.
static constexpr int SM_AH  = 0;
static constexpr int SM_BH  = 18432;
static constexpr int SM_TOT = 36864;

__global__ void __launch_bounds__(512, 2)
gemm_kernel(const float* __restrict__ x, int N) {
    extern __shared__ unsigned char smc[];
    const uint32_t sm = smem_u32(smc);
    const int tid  = threadIdx.x;
    const int lane = tid & 31;
    const int wid  = tid >> 5;
    const int wm   = wid >> 2;          // 0..3 -> M offset wm*32
    const int wn   = wid & 3;           // 0..3 -> N offset wn*32
    const int row0 = blockIdx.x * 128;

    const float4* X4 = (const float4*)x;          // row stride 64 float4
    const uint4*  WH = (const uint4*)g_wh;        // row = 32 uint4

    float acc[2][4][4];
    #pragma unroll
    for (int t = 0; t < 2; t++)
        #pragma unroll
        for (int nt = 0; nt < 4; nt++)
            #pragma unroll
            for (int j = 0; j < 4; j++) acc[t][nt][j] = 0.f;

    const int m = tid >> 2;             // producer row 0..127
    const int h = tid & 3;              // k-quarter (16 floats) within chunk
    const int rr = min(row0 + m, N - 1);

    const uint32_t a_adr0 = sm + SM_AH + (wm * 32 + 0  + (lane & 15)) * 144 + ((lane >> 4) << 4);
    const uint32_t a_adr1 = sm + SM_AH + (wm * 32 + 16 + (lane & 15)) * 144 + ((lane >> 4) << 4);
    const uint32_t b_row  = (uint32_t)(wn * 32 + ((lane >> 4) << 3) + (lane & 7));
    const uint32_t b_koff = (uint32_t)(((lane >> 3) & 1) << 4);
    const uint32_t b_adr  = sm + SM_BH + b_row * 144 + b_koff;

    for (int c = 0; c < 4; c++) {
        if (c > 0) __syncthreads();     // previous compute done before overwrite
        // ---- A: load 4 float4 -> fp16 -> STS (2x uint4) ----
        #pragma unroll
        for (int p = 0; p < 2; p++) {
            float4 f0 = X4[(size_t)rr * 64 + c * 16 + h * 4 + p * 2];
            float4 f1 = X4[(size_t)rr * 64 + c * 16 + h * 4 + p * 2 + 1];
            __half2 h0 = __floats2half2_rn(f0.x, f0.y);
            __half2 h1 = __floats2half2_rn(f0.z, f0.w);
            __half2 h2 = __floats2half2_rn(f1.x, f1.y);
            __half2 h3 = __floats2half2_rn(f1.z, f1.w);
            uint32_t off = (uint32_t)(m * 144 + h * 32 + p * 16);
            *(uint4*)(smc + SM_AH + off) = make_uint4(
                *(uint32_t*)&h0, *(uint32_t*)&h1, *(uint32_t*)&h2, *(uint32_t*)&h3);
        }
        // ---- B chunk copy, 1 uint4 per thread (L2-resident) ----
        {
            int n   = tid >> 2;
            int kq  = (tid & 3) * 2;
            uint32_t dst = (uint32_t)(n * 144 + kq * 16);
            uint4 v0 = WH[n * 32 + c * 8 + kq];
            uint4 v1 = WH[n * 32 + c * 8 + kq + 1];
            *(uint4*)(smc + SM_BH + dst)      = v0;
            *(uint4*)(smc + SM_BH + dst + 16) = v1;
        }
        __syncthreads();

        // ---- compute: 4 k16 steps, single MMA term ----
        #pragma unroll
        for (int ks = 0; ks < 4; ks++) {
            uint32_t ah0[4], ah1[4];
            LDSM_X4(ah0[0], ah0[1], ah0[2], ah0[3], a_adr0 + ks * 32);
            LDSM_X4(ah1[0], ah1[1], ah1[2], ah1[3], a_adr1 + ks * 32);
            #pragma unroll
            for (int j = 0; j < 2; j++) {      // 2 n16-groups
                uint32_t bh[4];
                LDSM_X4(bh[0], bh[1], bh[2], bh[3], b_adr + j * 16 * 144 + ks * 32);
                MMA_F16(acc[0][2 * j],     ah0, bh);
                MMA_F16(acc[1][2 * j],     ah1, bh);
                MMA_F16(acc[0][2 * j + 1], ah0, bh + 2);
                MMA_F16(acc[1][2 * j + 1], ah1, bh + 2);
            }
        }
    }

    // ---- epilogue: scale by dinv[row], write fp16 xwh ----
    uint32_t* xw = (uint32_t*)g_xwh;            // row stride 64 uint (half2)
    const int nb2 = wn * 16;                    // half2-base
    #pragma unroll
    for (int t = 0; t < 2; t++) {
        int r_lo = row0 + wm * 32 + t * 16 + (lane >> 2);
        int r_hi = r_lo + 8;
        float d_lo = (r_lo < N) ? g_dinv[r_lo] : 0.f;
        float d_hi = (r_hi < N) ? g_dinv[r_hi] : 0.f;
        #pragma unroll
        for (int nt = 0; nt < 4; nt++) {
            int ci = nb2 + nt * 4 + (lane & 3);
            if (r_lo < N) {
                __half2 p = __floats2half2_rn(acc[t][nt][0] * d_lo, acc[t][nt][1] * d_lo);
                xw[(size_t)r_lo * 64 + ci] = *(uint32_t*)&p;
            }
            if (r_hi < N) {
                __half2 p = __floats2half2_rn(acc[t][nt][2] * d_hi, acc[t][nt][3] * d_hi);
                xw[(size_t)r_hi * 64 + ci] = *(uint32_t*)&p;
            }
        }
    }
}

// ---------------------------------------------------------------------------
__device__ __forceinline__ void add_h4(float4& a, uint2 u) {
    float2 f0 = __half22float2(*(__half2*)&u.x);
    float2 f1 = __half22float2(*(__half2*)&u.y);
    a.x += f0.x; a.y += f0.y; a.z += f1.x; a.w += f1.y;
}

// 6) aggregation: one warp per node, fp16 gathers, fp32 accumulation.
//    8-wide unroll -> 8 outstanding L2 gathers per lane.
__global__ void __launch_bounds__(256) agg_kernel(const float* __restrict__ b,
                                                  float* __restrict__ out, int N) {
    int warp = (blockIdx.x * blockDim.x + threadIdx.x) >> 5;
    int lane = threadIdx.x & 31;
    if (warp >= N) return;
    int node = warp;

    const uint2* xw = (const uint2*)g_xwh;      // row stride 32 uint2
    float4 acc = make_float4(0.f, 0.f, 0.f, 0.f);
    add_h4(acc, xw[(size_t)node * 32 + lane]);  // self-loop
    float4 bb = ((const float4*)b)[lane];

    int e   = g_rowptr[node];
    int end = g_rowptr[node + 1];
    for (; e + 8 <= end; e += 8) {
        uint2 u[8];
        #pragma unroll
        for (int q = 0; q < 8; q++)
            u[q] = xw[(size_t)g_srcid[e + q] * 32 + lane];
        #pragma unroll
        for (int q = 0; q < 8; q++) add_h4(acc, u[q]);
    }
    if (e + 4 <= end) {
        uint2 u[4];
        #pragma unroll
        for (int q = 0; q < 4; q++)
            u[q] = xw[(size_t)g_srcid[e + q] * 32 + lane];
        #pragma unroll
        for (int q = 0; q < 4; q++) add_h4(acc, u[q]);
        e += 4;
    }
    for (; e < end; e++)
        add_h4(acc, xw[(size_t)g_srcid[e] * 32 + lane]);

    float di = g_dinv[node];
    float4 o;
    o.x = fmaxf(fmaf(di, acc.x, bb.x), 0.f);
    o.y = fmaxf(fmaf(di, acc.y, bb.y), 0.f);
    o.z = fmaxf(fmaf(di, acc.z, bb.z), 0.f);
    o.w = fmaxf(fmaf(di, acc.w, bb.w), 0.f);
    ((float4*)out)[(size_t)node * 32 + lane] = o;
}

// ---------------------------------------------------------------------------
extern "C" void kernel_launch(void* const* d_in, const int* in_sizes, int n_in,
                              void* d_out, int out_size) {
    const float* x  = (const float*)d_in[0];
    const void*  ei = d_in[1];                 // [2, E] int32 or int64 (probed)
    const float* W  = (const float*)d_in[2];
    const float* b  = (const float*)d_in[3];
    float*       out = (float*)d_out;

    const int N = in_sizes[0] / 256;   // 40000
    const int E = in_sizes[1] / 2;     // 640000

    cudaFuncSetAttribute(gemm_kernel, cudaFuncAttributeMaxDynamicSharedMemorySize, SM_TOT);

    // Order chosen so the ncu sample slot (4th launch) captures the GEMM.
    init_kernel<<<(N + 255) / 256, 256>>>((const int*)ei, W, N);
    count_kernel<<<(E + 255) / 256, 256>>>(ei, E, N);
    scan_kernel<<<1, 1024>>>(N);
    gemm_kernel<<<(N + 127) / 128, 512, SM_TOT>>>(x, N);
    scatter_kernel<<<(E + 255) / 256, 256>>>(ei, E, N);
    agg_kernel<<<(N * 32 + 255) / 256, 256>>>(b, out, N);
}